// round 1
// baseline (speedup 1.0000x reference)
#include <cuda_runtime.h>
#include <math.h>

// Problem constants (fixed shapes from reference)
constexpr int D  = 2048;          // feature dim
constexpr int M  = 16384;         // S*B = 2048*8 flattened rows
constexpr int TM = 128, TN = 128, TK = 16;

// Scratch for pp = tanh(...)  (M x D fp32 = 128 MiB). __device__ global:
// allocation-free per harness rules.
__device__ float g_pp[(size_t)M * D];

// ---------------------------------------------------------------------------
// Kernel 1: Z[m,e] = sum_d LI[m,d]*W1[e,d] + X[m,d]*W2[e,d]
//           pp[m,e] = tanh(Z + b1[e] + b2[e])
// Implemented as a single GEMM over virtual K = 2*D (tile-granular source switch).
// ---------------------------------------------------------------------------
__global__ __launch_bounds__(256, 2)
void k1_gemm_tanh(const float* __restrict__ LI, const float* __restrict__ X,
                  const float* __restrict__ W1, const float* __restrict__ W2,
                  const float* __restrict__ b1, const float* __restrict__ b2)
{
    __shared__ float As[TK][TM];   // transposed: As[k][m]
    __shared__ float Ws[TK][TN];   // transposed: Ws[k][e]

    const int tid = threadIdx.x;
    const int tx  = tid & 15;      // 0..15 -> e micro-tile
    const int ty  = tid >> 4;      // 0..15 -> m micro-tile
    const int mBase = blockIdx.y * TM;
    const int eBase = blockIdx.x * TN;

    float acc[8][8];
    #pragma unroll
    for (int i = 0; i < 8; ++i)
        #pragma unroll
        for (int j = 0; j < 8; ++j) acc[i][j] = 0.f;

    const int numTiles = (2 * D) / TK;
    for (int kt = 0; kt < numTiles; ++kt) {
        const int kcol = kt * TK;
        const float* Asrc;
        const float* Wsrc;
        int koff;
        if (kcol < D) { Asrc = LI; Wsrc = W1; koff = kcol; }
        else          { Asrc = X;  Wsrc = W2; koff = kcol - D; }

        __syncthreads();   // protect previous-iteration reads
        #pragma unroll
        for (int i = 0; i < 2; ++i) {
            const int s   = tid + i * 256;       // 512 float4 slots
            const int row = s >> 2;              // 0..127
            const int c4  = (s & 3) * 4;         // 0,4,8,12
            float4 av = *(const float4*)&Asrc[(size_t)(mBase + row) * D + koff + c4];
            As[c4 + 0][row] = av.x; As[c4 + 1][row] = av.y;
            As[c4 + 2][row] = av.z; As[c4 + 3][row] = av.w;
            float4 wv = *(const float4*)&Wsrc[(size_t)(eBase + row) * D + koff + c4];
            Ws[c4 + 0][row] = wv.x; Ws[c4 + 1][row] = wv.y;
            Ws[c4 + 2][row] = wv.z; Ws[c4 + 3][row] = wv.w;
        }
        __syncthreads();

        #pragma unroll
        for (int k = 0; k < TK; ++k) {
            float a[8], w[8];
            *(float4*)&a[0] = *(const float4*)&As[k][ty * 8];
            *(float4*)&a[4] = *(const float4*)&As[k][ty * 8 + 4];
            *(float4*)&w[0] = *(const float4*)&Ws[k][tx * 8];
            *(float4*)&w[4] = *(const float4*)&Ws[k][tx * 8 + 4];
            #pragma unroll
            for (int i = 0; i < 8; ++i)
                #pragma unroll
                for (int j = 0; j < 8; ++j)
                    acc[i][j] = fmaf(a[i], w[j], acc[i][j]);
        }
    }

    // Epilogue: bias + tanh -> g_pp
    float bsum[8];
    #pragma unroll
    for (int j = 0; j < 8; ++j) {
        const int e = eBase + tx * 8 + j;
        bsum[j] = b1[e] + b2[e];
    }
    #pragma unroll
    for (int i = 0; i < 8; ++i) {
        const int m = mBase + ty * 8 + i;
        float4 o0, o1;
        o0.x = tanhf(acc[i][0] + bsum[0]);
        o0.y = tanhf(acc[i][1] + bsum[1]);
        o0.z = tanhf(acc[i][2] + bsum[2]);
        o0.w = tanhf(acc[i][3] + bsum[3]);
        o1.x = tanhf(acc[i][4] + bsum[4]);
        o1.y = tanhf(acc[i][5] + bsum[5]);
        o1.z = tanhf(acc[i][6] + bsum[6]);
        o1.w = tanhf(acc[i][7] + bsum[7]);
        *(float4*)&g_pp[(size_t)m * D + eBase + tx * 8]     = o0;
        *(float4*)&g_pp[(size_t)m * D + eBase + tx * 8 + 4] = o1;
    }
}

// ---------------------------------------------------------------------------
// Kernel 2: G[m,e] = sigmoid(sum_d pp[m,d]*V[e,d] + bV[e]);  out = G * pe[m,e]
// ---------------------------------------------------------------------------
__global__ __launch_bounds__(256, 2)
void k2_gemm_gate(const float* __restrict__ Vw, const float* __restrict__ bV,
                  const float* __restrict__ pe, float* __restrict__ out)
{
    __shared__ float As[TK][TM];
    __shared__ float Ws[TK][TN];

    const int tid = threadIdx.x;
    const int tx  = tid & 15;
    const int ty  = tid >> 4;
    const int mBase = blockIdx.y * TM;
    const int eBase = blockIdx.x * TN;

    float acc[8][8];
    #pragma unroll
    for (int i = 0; i < 8; ++i)
        #pragma unroll
        for (int j = 0; j < 8; ++j) acc[i][j] = 0.f;

    const int numTiles = D / TK;
    for (int kt = 0; kt < numTiles; ++kt) {
        const int koff = kt * TK;
        __syncthreads();
        #pragma unroll
        for (int i = 0; i < 2; ++i) {
            const int s   = tid + i * 256;
            const int row = s >> 2;
            const int c4  = (s & 3) * 4;
            float4 av = *(const float4*)&g_pp[(size_t)(mBase + row) * D + koff + c4];
            As[c4 + 0][row] = av.x; As[c4 + 1][row] = av.y;
            As[c4 + 2][row] = av.z; As[c4 + 3][row] = av.w;
            float4 wv = *(const float4*)&Vw[(size_t)(eBase + row) * D + koff + c4];
            Ws[c4 + 0][row] = wv.x; Ws[c4 + 1][row] = wv.y;
            Ws[c4 + 2][row] = wv.z; Ws[c4 + 3][row] = wv.w;
        }
        __syncthreads();

        #pragma unroll
        for (int k = 0; k < TK; ++k) {
            float a[8], w[8];
            *(float4*)&a[0] = *(const float4*)&As[k][ty * 8];
            *(float4*)&a[4] = *(const float4*)&As[k][ty * 8 + 4];
            *(float4*)&w[0] = *(const float4*)&Ws[k][tx * 8];
            *(float4*)&w[4] = *(const float4*)&Ws[k][tx * 8 + 4];
            #pragma unroll
            for (int i = 0; i < 8; ++i)
                #pragma unroll
                for (int j = 0; j < 8; ++j)
                    acc[i][j] = fmaf(a[i], w[j], acc[i][j]);
        }
    }

    float bb[8];
    #pragma unroll
    for (int j = 0; j < 8; ++j) bb[j] = bV[eBase + tx * 8 + j];

    #pragma unroll
    for (int i = 0; i < 8; ++i) {
        const int m = mBase + ty * 8 + i;
        const size_t base = (size_t)m * D + eBase + tx * 8;
        float4 p0 = *(const float4*)&pe[base];
        float4 p1 = *(const float4*)&pe[base + 4];
        float4 o0, o1;
        o0.x = p0.x / (1.f + __expf(-(acc[i][0] + bb[0])));
        o0.y = p0.y / (1.f + __expf(-(acc[i][1] + bb[1])));
        o0.z = p0.z / (1.f + __expf(-(acc[i][2] + bb[2])));
        o0.w = p0.w / (1.f + __expf(-(acc[i][3] + bb[3])));
        o1.x = p1.x / (1.f + __expf(-(acc[i][4] + bb[4])));
        o1.y = p1.y / (1.f + __expf(-(acc[i][5] + bb[5])));
        o1.z = p1.z / (1.f + __expf(-(acc[i][6] + bb[6])));
        o1.w = p1.w / (1.f + __expf(-(acc[i][7] + bb[7])));
        *(float4*)&out[base]     = o0;
        *(float4*)&out[base + 4] = o1;
    }
}

// ---------------------------------------------------------------------------
// kernel_launch: inputs in metadata order:
// 0:x 1:layer_input 2:position_embedding 3:encoder_padding_mask 4:langs
// 5:W1 6:b1 7:W2 8:b2 9:V 10:bV      (mask/langs unused: all-zero/uniform path)
// ---------------------------------------------------------------------------
extern "C" void kernel_launch(void* const* d_in, const int* in_sizes, int n_in,
                              void* d_out, int out_size)
{
    const float* x  = (const float*)d_in[0];
    const float* li = (const float*)d_in[1];
    const float* pe = (const float*)d_in[2];
    const float* W1 = (const float*)d_in[5];
    const float* b1 = (const float*)d_in[6];
    const float* W2 = (const float*)d_in[7];
    const float* b2 = (const float*)d_in[8];
    const float* Vw = (const float*)d_in[9];
    const float* bV = (const float*)d_in[10];
    float* out = (float*)d_out;

    dim3 grid(D / TN, M / TM);   // (16, 128)
    dim3 block(256);
    k1_gemm_tanh<<<grid, block>>>(li, x, W1, W2, b1, b2);
    k2_gemm_gate<<<grid, block>>>(Vw, bV, pe, out);
}

// round 6
// speedup vs baseline: 4.0215x; 4.0215x over previous
#include <cuda_runtime.h>
#include <cstdint>
#include <cstddef>
#include <math.h>

// ---------------------------------------------------------------------------
// out[m,e], m<16384, e<2048
//   G1: pp = tanh( [LI|X](m,4096) . [W1;W2](e,4096)^T + b1 + b2 )
//   G2: out = sigmoid( pp . V^T + bV ) * pe
// tf32 mma.sync.m16n8k8 (arch-portable PTX; tcgen05 unavailable in the
// harness's compute_103 virtual-arch compile).
// CTA 128x256, 8 warps of 64x64, K-chunk 32, 4-stage cp.async pipeline.
// ---------------------------------------------------------------------------
constexpr int D     = 2048;
constexpr int M     = 16384;
constexpr int CTA_M = 128;
constexpr int CTA_N = 256;
constexpr int KC    = 32;                         // fp32 per K-chunk
constexpr int NSTG  = 4;
constexpr int A_WORDS = CTA_M * KC;               // 4096 (16 KB)
constexpr int B_WORDS = CTA_N * KC;               // 8192 (32 KB)
constexpr int STG_WORDS = A_WORDS + B_WORDS;      // 12288 (48 KB)
constexpr int SMEM_BYTES = NSTG * STG_WORDS * 4;  // 192 KB

__device__ float g_pp[(size_t)M * D];             // fp32 scratch for pp

// ---------------------------------------------------------------------------
__device__ __forceinline__ uint32_t smem_u32(const void* p) {
    uint32_t a;
    asm("{ .reg .u64 t; cvta.to.shared.u64 t, %1; cvt.u32.u64 %0, t; }"
        : "=r"(a) : "l"(p));
    return a;
}

__device__ __forceinline__ void cp_async16(uint32_t s, const void* g) {
    asm volatile("cp.async.cg.shared.global [%0], [%1], 16;" :: "r"(s), "l"(g));
}

__device__ __forceinline__ void ldsm4(uint32_t* r, uint32_t addr) {
    asm volatile("ldmatrix.sync.aligned.m8n8.x4.shared.b16 {%0,%1,%2,%3}, [%4];"
                 : "=r"(r[0]), "=r"(r[1]), "=r"(r[2]), "=r"(r[3]) : "r"(addr));
}

__device__ __forceinline__ uint32_t to_tf32(uint32_t x) {
    uint32_t d;
    asm("cvt.rna.tf32.f32 %0, %1;" : "=r"(d) : "f"(__uint_as_float(x)));
    return d;
}

__device__ __forceinline__ void mma_tf32(float* c, const uint32_t* a,
                                         uint32_t b0, uint32_t b1) {
    asm volatile(
        "mma.sync.aligned.m16n8k8.row.col.f32.tf32.tf32.f32 "
        "{%0,%1,%2,%3}, {%4,%5,%6,%7}, {%8,%9}, {%0,%1,%2,%3};"
        : "+f"(c[0]), "+f"(c[1]), "+f"(c[2]), "+f"(c[3])
        : "r"(a[0]), "r"(a[1]), "r"(a[2]), "r"(a[3]), "r"(b0), "r"(b1));
}

// swizzled word offset within a tile: row*32 + (kword ^ ((row&7)<<2))
__device__ __forceinline__ uint32_t swz(int row, int kw) {
    return (uint32_t)(row * 32 + (kw ^ ((row & 7) << 2)));
}

// Issue cp.async for one stage: A tile 128x32 + B tile 256x32 (both D-stride).
__device__ __forceinline__ void load_stage(uint32_t sbase,
                                           const float* __restrict__ Ap,
                                           const float* __restrict__ Bp,
                                           int mBase, int eBase, int koff, int tid) {
    #pragma unroll
    for (int i = 0; i < 4; i++) {                 // 1024 float4 / 256 thr
        int slot = tid + i * 256;
        int row = slot >> 3, c4 = slot & 7;
        cp_async16(sbase + swz(row, c4 * 4) * 4,
                   Ap + (size_t)(mBase + row) * D + koff + c4 * 4);
    }
    #pragma unroll
    for (int i = 0; i < 8; i++) {                 // 2048 float4 / 256 thr
        int slot = tid + i * 256;
        int row = slot >> 3, c4 = slot & 7;
        cp_async16(sbase + (A_WORDS + swz(row, c4 * 4)) * 4,
                   Bp + (size_t)(eBase + row) * D + koff + c4 * 4);
    }
}

// ---------------------------------------------------------------------------
// MODE 0: G1 (A = LI then X at kc>=64; B = W1 then W2; epi tanh -> g_pp)
// MODE 1: G2 (A = g_pp (device symbol), B = V; epi sigmoid * pe -> outp)
// ---------------------------------------------------------------------------
template <int MODE>
__global__ void __launch_bounds__(256, 1)
gemm_mma(const float* __restrict__ A0, const float* __restrict__ A1,
         const float* __restrict__ B0, const float* __restrict__ B1,
         const float* __restrict__ bias0, const float* __restrict__ bias1,
         const float* __restrict__ pe, float* __restrict__ outp, int NK)
{
    extern __shared__ float smem[];
    const uint32_t sb0 = smem_u32(smem);
    const int tid  = threadIdx.x;
    const int lane = tid & 31, wid = tid >> 5;
    const int wm = (wid & 1) * 64;                // warp m-offset (2 rows)
    const int wn = (wid >> 1) * 64;               // warp n-offset (4 cols)
    const int mBase = blockIdx.y * CTA_M;
    const int eBase = blockIdx.x * CTA_N;

    // MODE 1 sources its A operand from the device-symbol scratch directly.
    const float* Asrc0 = (MODE == 1) ? (const float*)g_pp : A0;
    const float* Asrc1 = (MODE == 1) ? (const float*)g_pp : A1;

    float acc[4][8][4];                           // [m16][n8][frag] = 128 regs
    #pragma unroll
    for (int i = 0; i < 4; i++)
        #pragma unroll
        for (int j = 0; j < 8; j++)
            #pragma unroll
            for (int k = 0; k < 4; k++) acc[i][j][k] = 0.f;

    // chunk -> source select (G1 switches tensors at kc==64; G2 never hits it)
    auto pick = [&](int kc, const float*& Ap, const float*& Bp, int& koff) {
        if (kc < 64) { Ap = Asrc0; Bp = B0; koff = kc * KC; }
        else         { Ap = Asrc1; Bp = B1; koff = kc * KC - D; }
    };

    #pragma unroll
    for (int s = 0; s < NSTG - 1; ++s) {          // prologue (NK >= 64 always)
        const float *Ap, *Bp; int koff;
        pick(s, Ap, Bp, koff);
        load_stage(sb0 + s * STG_WORDS * 4, Ap, Bp, mBase, eBase, koff, tid);
        asm volatile("cp.async.commit_group;");
    }

    #pragma unroll 1
    for (int kt = 0; kt < NK; ++kt) {
        if (kt > 0) __syncthreads();              // prev compute done before overwrite
        const int pf = kt + NSTG - 1;
        if (pf < NK) {
            const float *Ap, *Bp; int koff;
            pick(pf, Ap, Bp, koff);
            load_stage(sb0 + (pf % NSTG) * STG_WORDS * 4, Ap, Bp, mBase, eBase, koff, tid);
        }
        asm volatile("cp.async.commit_group;");
        asm volatile("cp.async.wait_group %0;" :: "n"(NSTG - 2));
        __syncthreads();

        const uint32_t stg = sb0 + (kt % NSTG) * STG_WORDS * 4;
        const int q = lane >> 3, r = lane & 7;

        #pragma unroll
        for (int ks2 = 0; ks2 < 2; ++ks2) {       // two k16 halves of the chunk
            // B frags: x4 ldmatrix covers 2 k8-steps per n8 tile
            uint32_t bf[8][4];
            #pragma unroll
            for (int nt = 0; nt < 8; ++nt) {
                const int nl = wn + nt * 8 + r;
                const int kf = ks2 * 16 + q * 4;
                ldsm4(bf[nt], stg + (A_WORDS + swz(nl, kf)) * 4);
            }
            #pragma unroll
            for (int nt = 0; nt < 8; ++nt)
                #pragma unroll
                for (int j = 0; j < 4; ++j) bf[nt][j] = to_tf32(bf[nt][j]);

            #pragma unroll
            for (int kk = 0; kk < 2; ++kk) {      // k8 steps
                const int ks = ks2 * 2 + kk;
                uint32_t af[4][4];
                #pragma unroll
                for (int mt = 0; mt < 4; ++mt) {
                    const int ml = wm + mt * 16 + (q & 1) * 8 + r;
                    const int kf = ks * 8 + (q >> 1) * 4;
                    ldsm4(af[mt], stg + swz(ml, kf) * 4);
                }
                #pragma unroll
                for (int mt = 0; mt < 4; ++mt)
                    #pragma unroll
                    for (int j = 0; j < 4; ++j) af[mt][j] = to_tf32(af[mt][j]);

                #pragma unroll
                for (int mt = 0; mt < 4; ++mt)
                    #pragma unroll
                    for (int nt = 0; nt < 8; ++nt)
                        mma_tf32(acc[mt][nt], af[mt], bf[nt][kk * 2], bf[nt][kk * 2 + 1]);
            }
        }
    }

    // ---------------- epilogue ----------------
    const int rq = lane >> 2, cq = lane & 3;      // frag row/col within tile
    #pragma unroll
    for (int mt = 0; mt < 4; ++mt) {
        const int row = mBase + wm + mt * 16 + rq;
        #pragma unroll
        for (int nt = 0; nt < 8; ++nt) {
            const int col = eBase + wn + nt * 8 + 2 * cq;
            const size_t o0 = (size_t)row * D + col;
            const size_t o1 = (size_t)(row + 8) * D + col;
            if (MODE == 0) {
                const float bs0 = bias0[col]     + bias1[col];
                const float bs1 = bias0[col + 1] + bias1[col + 1];
                float2 v0, v1;
                v0.x = tanhf(acc[mt][nt][0] + bs0);
                v0.y = tanhf(acc[mt][nt][1] + bs1);
                v1.x = tanhf(acc[mt][nt][2] + bs0);
                v1.y = tanhf(acc[mt][nt][3] + bs1);
                *(float2*)&g_pp[o0] = v0;
                *(float2*)&g_pp[o1] = v1;
            } else {
                const float bs0 = bias0[col];
                const float bs1 = bias0[col + 1];
                const float2 p0 = *(const float2*)&pe[o0];
                const float2 p1 = *(const float2*)&pe[o1];
                float2 v0, v1;
                v0.x = p0.x / (1.f + __expf(-(acc[mt][nt][0] + bs0)));
                v0.y = p0.y / (1.f + __expf(-(acc[mt][nt][1] + bs1)));
                v1.x = p1.x / (1.f + __expf(-(acc[mt][nt][2] + bs0)));
                v1.y = p1.y / (1.f + __expf(-(acc[mt][nt][3] + bs1)));
                *(float2*)&outp[o0] = v0;
                *(float2*)&outp[o1] = v1;
            }
        }
    }
}

// ---------------------------------------------------------------------------
// Inputs (metadata order): 0:x 1:layer_input 2:position_embedding
// 3:encoder_padding_mask 4:langs 5:W1 6:b1 7:W2 8:b2 9:V 10:bV
// ---------------------------------------------------------------------------
extern "C" void kernel_launch(void* const* d_in, const int* in_sizes, int n_in,
                              void* d_out, int out_size)
{
    const float* x  = (const float*)d_in[0];
    const float* li = (const float*)d_in[1];
    const float* pe = (const float*)d_in[2];
    const float* W1 = (const float*)d_in[5];
    const float* b1 = (const float*)d_in[6];
    const float* W2 = (const float*)d_in[7];
    const float* b2 = (const float*)d_in[8];
    const float* Vw = (const float*)d_in[9];
    const float* bV = (const float*)d_in[10];
    float* out = (float*)d_out;

    cudaFuncSetAttribute(gemm_mma<0>, cudaFuncAttributeMaxDynamicSharedMemorySize, SMEM_BYTES);
    cudaFuncSetAttribute(gemm_mma<1>, cudaFuncAttributeMaxDynamicSharedMemorySize, SMEM_BYTES);

    dim3 grid(D / CTA_N, M / CTA_M);   // (8, 128)
    gemm_mma<0><<<grid, 256, SMEM_BYTES>>>(li, x, W1, W2, b1, b2, nullptr, nullptr, 2 * D / KC);
    gemm_mma<1><<<grid, 256, SMEM_BYTES>>>(nullptr, nullptr, Vw, Vw, bV, nullptr, pe, out, D / KC);
}

// round 10
// speedup vs baseline: 4.1835x; 1.0403x over previous
#include <cuda_runtime.h>
#include <cstdint>
#include <cstddef>
#include <math.h>

// ---------------------------------------------------------------------------
// out[m,e], m<16384, e<2048
//   G1: pp = tanh( [LI|X](m,4096) . [W1;W2](e,4096)^T + b1 + b2 )
//   G2: out = sigmoid( pp . V^T + bV ) * pe
// tf32 mma.sync.m16n8k8. All operands pre-rounded to tf32 in memory
// (prepass for LI/X/W1/W2/V; G1 epilogue rounds pp) so the GEMM mainloop
// issues ZERO cvt instructions (R6 ncu: alu pipe 31.8% from per-fragment
// cvt.rna.tf32 was throttling tensor pipe at 53%).
// CTA 128x256, 8 warps of 64x64, K-chunk 32, 4-stage cp.async pipeline.
// No host API calls in kernel_launch except kernel launches (scratch
// pointers resolved device-side from __device__ symbols).
// ---------------------------------------------------------------------------
constexpr int D     = 2048;
constexpr int M     = 16384;
constexpr int CTA_M = 128;
constexpr int CTA_N = 256;
constexpr int KC    = 32;
constexpr int NSTG  = 4;
constexpr int A_WORDS = CTA_M * KC;               // 4096 (16 KB)
constexpr int B_WORDS = CTA_N * KC;               // 8192 (32 KB)
constexpr int STG_WORDS = A_WORDS + B_WORDS;      // 12288 (48 KB)
constexpr int SMEM_BYTES = NSTG * STG_WORDS * 4;  // 192 KB

__device__ float g_pp[(size_t)M * D];             // tf32-rounded pp (128 MB)
__device__ float g_act[2 * (size_t)M * D];        // tf32-rounded [LI | X] (256 MB)
__device__ float g_w[3 * (size_t)D * D];          // tf32-rounded [W1 | W2 | V] (48 MB)

// ---------------------------------------------------------------------------
__device__ __forceinline__ uint32_t smem_u32(const void* p) {
    uint32_t a;
    asm("{ .reg .u64 t; cvta.to.shared.u64 t, %1; cvt.u32.u64 %0, t; }"
        : "=r"(a) : "l"(p));
    return a;
}

__device__ __forceinline__ void cp_async16(uint32_t s, const void* g) {
    asm volatile("cp.async.cg.shared.global [%0], [%1], 16;" :: "r"(s), "l"(g));
}

__device__ __forceinline__ void ldsm4(uint32_t* r, uint32_t addr) {
    asm volatile("ldmatrix.sync.aligned.m8n8.x4.shared.b16 {%0,%1,%2,%3}, [%4];"
                 : "=r"(r[0]), "=r"(r[1]), "=r"(r[2]), "=r"(r[3]) : "r"(addr));
}

__device__ __forceinline__ float to_tf32_f(float x) {
    uint32_t d;
    asm("cvt.rna.tf32.f32 %0, %1;" : "=r"(d) : "f"(x));
    return __uint_as_float(d);
}

__device__ __forceinline__ void mma_tf32(float* c, const uint32_t* a,
                                         uint32_t b0, uint32_t b1) {
    asm volatile(
        "mma.sync.aligned.m16n8k8.row.col.f32.tf32.tf32.f32 "
        "{%0,%1,%2,%3}, {%4,%5,%6,%7}, {%8,%9}, {%0,%1,%2,%3};"
        : "+f"(c[0]), "+f"(c[1]), "+f"(c[2]), "+f"(c[3])
        : "r"(a[0]), "r"(a[1]), "r"(a[2]), "r"(a[3]), "r"(b0), "r"(b1));
}

// swizzled word offset within a tile: row*32 + (kword ^ ((row&7)<<2))
__device__ __forceinline__ uint32_t swz(int row, int kw) {
    return (uint32_t)(row * 32 + (kw ^ ((row & 7) << 2)));
}

// ---------------------------------------------------------------------------
// Prepass: round src into scratch. DST selector resolves the __device__
// symbol pointer on-device (no cudaGetSymbolAddress in the launch path).
//   0: g_act[0]   1: g_act[M*D]   2: g_w[0]   3: g_w[D*D]   4: g_w[2*D*D]
// ---------------------------------------------------------------------------
__global__ void __launch_bounds__(256)
preround(const float* __restrict__ src, int dst_sel, size_t n4) {
    float* dst;
    switch (dst_sel) {
        case 0:  dst = g_act; break;
        case 1:  dst = g_act + (size_t)M * D; break;
        case 2:  dst = g_w; break;
        case 3:  dst = g_w + (size_t)D * D; break;
        default: dst = g_w + 2 * (size_t)D * D; break;
    }
    size_t i = (size_t)blockIdx.x * blockDim.x + threadIdx.x;
    size_t stride = (size_t)gridDim.x * blockDim.x;
    for (; i < n4; i += stride) {
        float4 v = ((const float4*)src)[i];
        v.x = to_tf32_f(v.x); v.y = to_tf32_f(v.y);
        v.z = to_tf32_f(v.z); v.w = to_tf32_f(v.w);
        ((float4*)dst)[i] = v;
    }
}

// ---------------------------------------------------------------------------
// Issue cp.async for one stage: A tile 128x32 + B tile 256x32 (both D-stride).
// ---------------------------------------------------------------------------
__device__ __forceinline__ void load_stage(uint32_t sbase,
                                           const float* __restrict__ Ap,
                                           const float* __restrict__ Bp,
                                           int mBase, int eBase, int koff, int tid) {
    #pragma unroll
    for (int i = 0; i < 4; i++) {
        int slot = tid + i * 256;
        int row = slot >> 3, c4 = slot & 7;
        cp_async16(sbase + swz(row, c4 * 4) * 4,
                   Ap + (size_t)(mBase + row) * D + koff + c4 * 4);
    }
    #pragma unroll
    for (int i = 0; i < 8; i++) {
        int slot = tid + i * 256;
        int row = slot >> 3, c4 = slot & 7;
        cp_async16(sbase + (A_WORDS + swz(row, c4 * 4)) * 4,
                   Bp + (size_t)(eBase + row) * D + koff + c4 * 4);
    }
}

// ---------------------------------------------------------------------------
// MODE 0: G1 (A = g_act halves; B = g_w[0],g_w[1]; epi tanh+round -> g_pp)
// MODE 1: G2 (A = g_pp; B = g_w[2]; epi sigmoid * pe -> outp)
// ---------------------------------------------------------------------------
template <int MODE>
__global__ void __launch_bounds__(256, 1)
gemm_mma(const float* __restrict__ bias0, const float* __restrict__ bias1,
         const float* __restrict__ pe, float* __restrict__ outp, int NK)
{
    extern __shared__ float smem[];
    const uint32_t sb0 = smem_u32(smem);
    const int tid  = threadIdx.x;
    const int lane = tid & 31, wid = tid >> 5;
    const int wm = (wid & 1) * 64;
    const int wn = (wid >> 1) * 64;
    const int mBase = blockIdx.y * CTA_M;
    const int eBase = blockIdx.x * CTA_N;

    const float* Asrc0 = (MODE == 1) ? g_pp : g_act;
    const float* Asrc1 = (MODE == 1) ? g_pp : g_act + (size_t)M * D;
    const float* Bsrc0 = (MODE == 1) ? g_w + 2 * (size_t)D * D : g_w;
    const float* Bsrc1 = (MODE == 1) ? g_w + 2 * (size_t)D * D : g_w + (size_t)D * D;

    float acc[4][8][4];
    #pragma unroll
    for (int i = 0; i < 4; i++)
        #pragma unroll
        for (int j = 0; j < 8; j++)
            #pragma unroll
            for (int k = 0; k < 4; k++) acc[i][j][k] = 0.f;

    auto pick = [&](int kc, const float*& Ap, const float*& Bp, int& koff) {
        if (kc < 64) { Ap = Asrc0; Bp = Bsrc0; koff = kc * KC; }
        else         { Ap = Asrc1; Bp = Bsrc1; koff = kc * KC - D; }
    };

    #pragma unroll
    for (int s = 0; s < NSTG - 1; ++s) {
        const float *Ap, *Bp; int koff;
        pick(s, Ap, Bp, koff);
        load_stage(sb0 + s * STG_WORDS * 4, Ap, Bp, mBase, eBase, koff, tid);
        asm volatile("cp.async.commit_group;");
    }

    #pragma unroll 1
    for (int kt = 0; kt < NK; ++kt) {
        if (kt > 0) __syncthreads();
        const int pf = kt + NSTG - 1;
        if (pf < NK) {
            const float *Ap, *Bp; int koff;
            pick(pf, Ap, Bp, koff);
            load_stage(sb0 + (pf % NSTG) * STG_WORDS * 4, Ap, Bp, mBase, eBase, koff, tid);
        }
        asm volatile("cp.async.commit_group;");
        asm volatile("cp.async.wait_group %0;" :: "n"(NSTG - 2));
        __syncthreads();

        const uint32_t stg = sb0 + (kt % NSTG) * STG_WORDS * 4;
        const int q = lane >> 3, r = lane & 7;

        #pragma unroll
        for (int ks2 = 0; ks2 < 2; ++ks2) {
            uint32_t bf[8][4];
            #pragma unroll
            for (int nt = 0; nt < 8; ++nt) {
                const int nl = wn + nt * 8 + r;
                const int kf = ks2 * 16 + q * 4;
                ldsm4(bf[nt], stg + (A_WORDS + swz(nl, kf)) * 4);
            }

            #pragma unroll
            for (int kk = 0; kk < 2; ++kk) {
                const int ks = ks2 * 2 + kk;
                uint32_t af[4][4];
                #pragma unroll
                for (int mt = 0; mt < 4; ++mt) {
                    const int ml = wm + mt * 16 + (q & 1) * 8 + r;
                    const int kf = ks * 8 + (q >> 1) * 4;
                    ldsm4(af[mt], stg + swz(ml, kf) * 4);
                }
                #pragma unroll
                for (int mt = 0; mt < 4; ++mt)
                    #pragma unroll
                    for (int nt = 0; nt < 8; ++nt)
                        mma_tf32(acc[mt][nt], af[mt], bf[nt][kk * 2], bf[nt][kk * 2 + 1]);
            }
        }
    }

    // ---------------- epilogue ----------------
    const int rq = lane >> 2, cq = lane & 3;
    #pragma unroll
    for (int mt = 0; mt < 4; ++mt) {
        const int row = mBase + wm + mt * 16 + rq;
        #pragma unroll
        for (int nt = 0; nt < 8; ++nt) {
            const int col = eBase + wn + nt * 8 + 2 * cq;
            const size_t o0 = (size_t)row * D + col;
            const size_t o1 = (size_t)(row + 8) * D + col;
            if (MODE == 0) {
                const float bs0 = bias0[col]     + bias1[col];
                const float bs1 = bias0[col + 1] + bias1[col + 1];
                float2 v0, v1;
                // round here so G2 needs no per-fragment cvt (numerically
                // identical to rounding at G2's operand load)
                v0.x = to_tf32_f(tanhf(acc[mt][nt][0] + bs0));
                v0.y = to_tf32_f(tanhf(acc[mt][nt][1] + bs1));
                v1.x = to_tf32_f(tanhf(acc[mt][nt][2] + bs0));
                v1.y = to_tf32_f(tanhf(acc[mt][nt][3] + bs1));
                *(float2*)&g_pp[o0] = v0;
                *(float2*)&g_pp[o1] = v1;
            } else {
                const float bs0 = bias0[col];
                const float bs1 = bias0[col + 1];
                const float2 p0 = *(const float2*)&pe[o0];
                const float2 p1 = *(const float2*)&pe[o1];
                float2 v0, v1;
                v0.x = p0.x / (1.f + __expf(-(acc[mt][nt][0] + bs0)));
                v0.y = p0.y / (1.f + __expf(-(acc[mt][nt][1] + bs1)));
                v1.x = p1.x / (1.f + __expf(-(acc[mt][nt][2] + bs0)));
                v1.y = p1.y / (1.f + __expf(-(acc[mt][nt][3] + bs1)));
                *(float2*)&outp[o0] = v0;
                *(float2*)&outp[o1] = v1;
            }
        }
    }
}

// ---------------------------------------------------------------------------
// Inputs (metadata order): 0:x 1:layer_input 2:position_embedding
// 3:encoder_padding_mask 4:langs 5:W1 6:b1 7:W2 8:b2 9:V 10:bV
// ---------------------------------------------------------------------------
extern "C" void kernel_launch(void* const* d_in, const int* in_sizes, int n_in,
                              void* d_out, int out_size)
{
    const float* x  = (const float*)d_in[0];
    const float* li = (const float*)d_in[1];
    const float* pe = (const float*)d_in[2];
    const float* W1 = (const float*)d_in[5];
    const float* b1 = (const float*)d_in[6];
    const float* W2 = (const float*)d_in[7];
    const float* b2 = (const float*)d_in[8];
    const float* Vw = (const float*)d_in[9];
    const float* bV = (const float*)d_in[10];
    float* out = (float*)d_out;

    static bool attr_done = false;
    if (!attr_done) {
        cudaFuncSetAttribute(gemm_mma<0>, cudaFuncAttributeMaxDynamicSharedMemorySize, SMEM_BYTES);
        cudaFuncSetAttribute(gemm_mma<1>, cudaFuncAttributeMaxDynamicSharedMemorySize, SMEM_BYTES);
        attr_done = true;
    }

    const size_t MD4 = (size_t)M * D / 4;
    const size_t DD4 = (size_t)D * D / 4;
    preround<<<2048, 256>>>(li, 0, MD4);
    preround<<<2048, 256>>>(x,  1, MD4);
    preround<<<512, 256>>>(W1, 2, DD4);
    preround<<<512, 256>>>(W2, 3, DD4);
    preround<<<512, 256>>>(Vw, 4, DD4);

    dim3 grid(D / CTA_N, M / CTA_M);   // (8, 128)
    gemm_mma<0><<<grid, 256, SMEM_BYTES>>>(b1, b2, nullptr, nullptr, 2 * D / KC);
    gemm_mma<1><<<grid, 256, SMEM_BYTES>>>(bV, nullptr, pe, out, D / KC);
}

// round 14
// speedup vs baseline: 4.5401x; 1.0852x over previous
#include <cuda_runtime.h>
#include <cstdint>
#include <cstddef>
#include <math.h>

// ---------------------------------------------------------------------------
// out[m,e], m<16384, e<2048
//   G1: pp = tanh( [LI|X](m,4096) . [W1;W2](e,4096)^T + b1 + b2 )
//   G2: out = sigmoid( pp . V^T + bV ) * pe
// tf32 mma.sync.m16n8k8, operands pre-rounded in memory (zero mainloop cvt).
// R11: single barrier per K-chunk, cp.async interleaved into MMA stream,
// register double-buffered A fragments (R10 showed tensor pipe ~53% with
// ~1600 cyc/chunk of overlap-recoverable bubbles).
// CTA 128x256, 8 warps of 64x64, K-chunk 32, 4-stage cp.async pipeline.
// ---------------------------------------------------------------------------
constexpr int D     = 2048;
constexpr int M     = 16384;
constexpr int CTA_M = 128;
constexpr int CTA_N = 256;
constexpr int KC    = 32;
constexpr int NSTG  = 4;
constexpr int A_WORDS = CTA_M * KC;               // 4096 (16 KB)
constexpr int B_WORDS = CTA_N * KC;               // 8192 (32 KB)
constexpr int STG_WORDS = A_WORDS + B_WORDS;      // 12288 (48 KB)
constexpr int SMEM_BYTES = NSTG * STG_WORDS * 4;  // 192 KB

__device__ float g_pp[(size_t)M * D];             // tf32-rounded pp
__device__ float g_act[2 * (size_t)M * D];        // tf32-rounded [LI | X]
__device__ float g_w[3 * (size_t)D * D];          // tf32-rounded [W1 | W2 | V]

// ---------------------------------------------------------------------------
__device__ __forceinline__ uint32_t smem_u32(const void* p) {
    uint32_t a;
    asm("{ .reg .u64 t; cvta.to.shared.u64 t, %1; cvt.u32.u64 %0, t; }"
        : "=r"(a) : "l"(p));
    return a;
}

__device__ __forceinline__ void cp_async16(uint32_t s, const void* g) {
    asm volatile("cp.async.cg.shared.global [%0], [%1], 16;" :: "r"(s), "l"(g));
}

__device__ __forceinline__ void ldsm4(uint32_t* r, uint32_t addr) {
    asm volatile("ldmatrix.sync.aligned.m8n8.x4.shared.b16 {%0,%1,%2,%3}, [%4];"
                 : "=r"(r[0]), "=r"(r[1]), "=r"(r[2]), "=r"(r[3]) : "r"(addr));
}

__device__ __forceinline__ float to_tf32_f(float x) {
    uint32_t d;
    asm("cvt.rna.tf32.f32 %0, %1;" : "=r"(d) : "f"(x));
    return __uint_as_float(d);
}

__device__ __forceinline__ void mma_tf32(float* c, const uint32_t* a,
                                         uint32_t b0, uint32_t b1) {
    asm volatile(
        "mma.sync.aligned.m16n8k8.row.col.f32.tf32.tf32.f32 "
        "{%0,%1,%2,%3}, {%4,%5,%6,%7}, {%8,%9}, {%0,%1,%2,%3};"
        : "+f"(c[0]), "+f"(c[1]), "+f"(c[2]), "+f"(c[3])
        : "r"(a[0]), "r"(a[1]), "r"(a[2]), "r"(a[3]), "r"(b0), "r"(b1));
}

// swizzled word offset within a tile: row*32 + (kword ^ ((row&7)<<2))
__device__ __forceinline__ uint32_t swz(int row, int kw) {
    return (uint32_t)(row * 32 + (kw ^ ((row & 7) << 2)));
}

// ---------------------------------------------------------------------------
// Prepass: round src into scratch (device-resolved dst).
//   0: g_act[0]  1: g_act[M*D]  2: g_w[0]  3: g_w[D*D]  4: g_w[2*D*D]
// ---------------------------------------------------------------------------
__global__ void __launch_bounds__(256)
preround(const float* __restrict__ src, int dst_sel, size_t n4) {
    float* dst;
    switch (dst_sel) {
        case 0:  dst = g_act; break;
        case 1:  dst = g_act + (size_t)M * D; break;
        case 2:  dst = g_w; break;
        case 3:  dst = g_w + (size_t)D * D; break;
        default: dst = g_w + 2 * (size_t)D * D; break;
    }
    size_t i = (size_t)blockIdx.x * blockDim.x + threadIdx.x;
    size_t stride = (size_t)gridDim.x * blockDim.x;
    for (; i < n4; i += stride) {
        float4 v = ((const float4*)src)[i];
        v.x = to_tf32_f(v.x); v.y = to_tf32_f(v.y);
        v.z = to_tf32_f(v.z); v.w = to_tf32_f(v.w);
        ((float4*)dst)[i] = v;
    }
}

// ---------------------------------------------------------------------------
// Stage-load halves (A tile 128x32: 4 cp.async/thr; B tile 256x32: 8/thr)
// ---------------------------------------------------------------------------
__device__ __forceinline__ void load_A(uint32_t sbase, const float* __restrict__ Ap,
                                       int mBase, int koff, int tid) {
    #pragma unroll
    for (int i = 0; i < 4; i++) {
        int slot = tid + i * 256;
        int row = slot >> 3, c4 = slot & 7;
        cp_async16(sbase + swz(row, c4 * 4) * 4,
                   Ap + (size_t)(mBase + row) * D + koff + c4 * 4);
    }
}
__device__ __forceinline__ void load_B(uint32_t sbase, const float* __restrict__ Bp,
                                       int eBase, int koff, int tid) {
    #pragma unroll
    for (int i = 0; i < 8; i++) {
        int slot = tid + i * 256;
        int row = slot >> 3, c4 = slot & 7;
        cp_async16(sbase + (A_WORDS + swz(row, c4 * 4)) * 4,
                   Bp + (size_t)(eBase + row) * D + koff + c4 * 4);
    }
}

// ---------------------------------------------------------------------------
// MODE 0: G1 (A = g_act halves; B = g_w[0],g_w[1]; epi tanh+round -> g_pp)
// MODE 1: G2 (A = g_pp; B = g_w[2]; epi sigmoid * pe -> outp)
// ---------------------------------------------------------------------------
template <int MODE>
__global__ void __launch_bounds__(256, 1)
gemm_mma(const float* __restrict__ bias0, const float* __restrict__ bias1,
         const float* __restrict__ pe, float* __restrict__ outp, int NK)
{
    extern __shared__ float smem[];
    const uint32_t sb0 = smem_u32(smem);
    const int tid  = threadIdx.x;
    const int lane = tid & 31, wid = tid >> 5;
    const int wm = (wid & 1) * 64;
    const int wn = (wid >> 1) * 64;
    const int mBase = blockIdx.y * CTA_M;
    const int eBase = blockIdx.x * CTA_N;

    const float* Asrc0 = (MODE == 1) ? g_pp : g_act;
    const float* Asrc1 = (MODE == 1) ? g_pp : g_act + (size_t)M * D;
    const float* Bsrc0 = (MODE == 1) ? g_w + 2 * (size_t)D * D : g_w;
    const float* Bsrc1 = (MODE == 1) ? g_w + 2 * (size_t)D * D : g_w + (size_t)D * D;

    float acc[4][8][4];
    #pragma unroll
    for (int i = 0; i < 4; i++)
        #pragma unroll
        for (int j = 0; j < 8; j++)
            #pragma unroll
            for (int k = 0; k < 4; k++) acc[i][j][k] = 0.f;

    auto pick = [&](int kc, const float*& Ap, const float*& Bp, int& koff) {
        if (kc < 64) { Ap = Asrc0; Bp = Bsrc0; koff = kc * KC; }
        else         { Ap = Asrc1; Bp = Bsrc1; koff = kc * KC - D; }
    };

    #pragma unroll
    for (int s = 0; s < NSTG - 1; ++s) {
        const float *Ap, *Bp; int koff;
        pick(s, Ap, Bp, koff);
        load_A(sb0 + s * STG_WORDS * 4, Ap, mBase, koff, tid);
        load_B(sb0 + s * STG_WORDS * 4, Bp, eBase, koff, tid);
        asm volatile("cp.async.commit_group;");
    }

    const int q = lane >> 3, r = lane & 7;
    // precomputed swizzled fragment base offsets (bytes)
    uint32_t aoff[4], boff[8];
    #pragma unroll
    for (int mt = 0; mt < 4; ++mt)
        aoff[mt] = swz(wm + mt * 16 + (q & 1) * 8 + r, (q >> 1) * 4) * 4;
    #pragma unroll
    for (int nt = 0; nt < 8; ++nt)
        boff[nt] = (A_WORDS + swz(wn + nt * 8 + r, q * 4)) * 4;
    // XOR deltas to move kf by +8 words (A k-step) / +16 words (B half step):
    // swz flips only low 7 bits of word index via kf ^ ..., kf base is q-dep;
    // moving kf by +8 or +16 words toggles word-offset bits -> byte XOR.
    const uint32_t AK8  = 8 * 4;    // +8 words within same row: pure offset add in
    const uint32_t BK16 = 16 * 4;   // unswizzled kw; swz xors bits>=4 words unchanged
    // NOTE: swz(row, kw) = row*32 + (kw ^ s). (kw+8)^s == (kw^s)+8 only if no carry
    // into bit3 group... kw in {0,4}+8k, s multiple of 4 in [0,28]: XOR of bit>=2..
    // safest: recompute full swz per use below instead of deltas for A; B halves
    // use kf = 0/16 + q*4 -> adding 16 words toggles bit4 of kw which passes
    // through XOR untouched only if s < 16... s = ((row&7)<<2) can be >=16.
    // => recompute exact addresses (cheap IMADs, hoisted by compiler).
    (void)AK8; (void)BK16;

    #pragma unroll 1
    for (int kt = 0; kt < NK; ++kt) {
        asm volatile("cp.async.wait_group %0;" :: "n"(NSTG - 2));
        __syncthreads();

        const uint32_t stg = sb0 + (kt & 3) * STG_WORDS * 4;
        const int pf = kt + NSTG - 1;
        const bool do_pf = pf < NK;
        const float *Ap = nullptr, *Bp = nullptr; int koff = 0;
        if (do_pf) pick(pf, Ap, Bp, koff);
        const uint32_t pstg = sb0 + (pf & 3) * STG_WORDS * 4;

        uint32_t bf[8][4], af0[4][4], af1[4][4];

        // ---- B half 0 (ks 0..1) + A ks=0 ----
        #pragma unroll
        for (int nt = 0; nt < 8; ++nt)
            ldsm4(bf[nt], stg + (A_WORDS + swz(wn + nt * 8 + r, q * 4)) * 4);
        #pragma unroll
        for (int mt = 0; mt < 4; ++mt)
            ldsm4(af0[mt], stg + swz(wm + mt * 16 + (q & 1) * 8 + r, (q >> 1) * 4) * 4);
        if (do_pf) load_A(pstg, Ap, mBase, koff, tid);      // overlap LSU w/ MMA
        #pragma unroll
        for (int mt = 0; mt < 4; ++mt)
            ldsm4(af1[mt], stg + swz(wm + mt * 16 + (q & 1) * 8 + r, 8 + (q >> 1) * 4) * 4);

        #pragma unroll
        for (int mt = 0; mt < 4; ++mt)
            #pragma unroll
            for (int nt = 0; nt < 8; ++nt)
                mma_tf32(acc[mt][nt], af0[mt], bf[nt][0], bf[nt][1]);
        if (do_pf) load_B(pstg, Bp, eBase, koff, tid);
        #pragma unroll
        for (int mt = 0; mt < 4; ++mt)
            #pragma unroll
            for (int nt = 0; nt < 8; ++nt)
                mma_tf32(acc[mt][nt], af1[mt], bf[nt][2], bf[nt][3]);
        asm volatile("cp.async.commit_group;");

        // ---- B half 1 (ks 2..3) ----
        #pragma unroll
        for (int nt = 0; nt < 8; ++nt)
            ldsm4(bf[nt], stg + (A_WORDS + swz(wn + nt * 8 + r, 16 + q * 4)) * 4);
        #pragma unroll
        for (int mt = 0; mt < 4; ++mt)
            ldsm4(af0[mt], stg + swz(wm + mt * 16 + (q & 1) * 8 + r, 16 + (q >> 1) * 4) * 4);
        #pragma unroll
        for (int mt = 0; mt < 4; ++mt)
            ldsm4(af1[mt], stg + swz(wm + mt * 16 + (q & 1) * 8 + r, 24 + (q >> 1) * 4) * 4);

        #pragma unroll
        for (int mt = 0; mt < 4; ++mt)
            #pragma unroll
            for (int nt = 0; nt < 8; ++nt)
                mma_tf32(acc[mt][nt], af0[mt], bf[nt][0], bf[nt][1]);
        #pragma unroll
        for (int mt = 0; mt < 4; ++mt)
            #pragma unroll
            for (int nt = 0; nt < 8; ++nt)
                mma_tf32(acc[mt][nt], af1[mt], bf[nt][2], bf[nt][3]);
    }

    // ---------------- epilogue ----------------
    const int rq = lane >> 2, cq = lane & 3;
    #pragma unroll
    for (int mt = 0; mt < 4; ++mt) {
        const int row = mBase + wm + mt * 16 + rq;
        #pragma unroll
        for (int nt = 0; nt < 8; ++nt) {
            const int col = eBase + wn + nt * 8 + 2 * cq;
            const size_t o0 = (size_t)row * D + col;
            const size_t o1 = (size_t)(row + 8) * D + col;
            if (MODE == 0) {
                const float bs0 = bias0[col]     + bias1[col];
                const float bs1 = bias0[col + 1] + bias1[col + 1];
                float2 v0, v1;
                v0.x = to_tf32_f(tanhf(acc[mt][nt][0] + bs0));
                v0.y = to_tf32_f(tanhf(acc[mt][nt][1] + bs1));
                v1.x = to_tf32_f(tanhf(acc[mt][nt][2] + bs0));
                v1.y = to_tf32_f(tanhf(acc[mt][nt][3] + bs1));
                *(float2*)&g_pp[o0] = v0;
                *(float2*)&g_pp[o1] = v1;
            } else {
                const float bs0 = bias0[col];
                const float bs1 = bias0[col + 1];
                const float2 p0 = *(const float2*)&pe[o0];
                const float2 p1 = *(const float2*)&pe[o1];
                float2 v0, v1;
                v0.x = p0.x / (1.f + __expf(-(acc[mt][nt][0] + bs0)));
                v0.y = p0.y / (1.f + __expf(-(acc[mt][nt][1] + bs1)));
                v1.x = p1.x / (1.f + __expf(-(acc[mt][nt][2] + bs0)));
                v1.y = p1.y / (1.f + __expf(-(acc[mt][nt][3] + bs1)));
                *(float2*)&outp[o0] = v0;
                *(float2*)&outp[o1] = v1;
            }
        }
    }
}

// ---------------------------------------------------------------------------
// Inputs (metadata order): 0:x 1:layer_input 2:position_embedding
// 3:encoder_padding_mask 4:langs 5:W1 6:b1 7:W2 8:b2 9:V 10:bV
// ---------------------------------------------------------------------------
extern "C" void kernel_launch(void* const* d_in, const int* in_sizes, int n_in,
                              void* d_out, int out_size)
{
    const float* x  = (const float*)d_in[0];
    const float* li = (const float*)d_in[1];
    const float* pe = (const float*)d_in[2];
    const float* W1 = (const float*)d_in[5];
    const float* b1 = (const float*)d_in[6];
    const float* W2 = (const float*)d_in[7];
    const float* b2 = (const float*)d_in[8];
    const float* Vw = (const float*)d_in[9];
    const float* bV = (const float*)d_in[10];
    float* out = (float*)d_out;

    static bool attr_done = false;
    if (!attr_done) {
        cudaFuncSetAttribute(gemm_mma<0>, cudaFuncAttributeMaxDynamicSharedMemorySize, SMEM_BYTES);
        cudaFuncSetAttribute(gemm_mma<1>, cudaFuncAttributeMaxDynamicSharedMemorySize, SMEM_BYTES);
        attr_done = true;
    }

    const size_t MD4 = (size_t)M * D / 4;
    const size_t DD4 = (size_t)D * D / 4;
    preround<<<2048, 256>>>(li, 0, MD4);
    preround<<<2048, 256>>>(x,  1, MD4);
    preround<<<512, 256>>>(W1, 2, DD4);
    preround<<<512, 256>>>(W2, 3, DD4);
    preround<<<512, 256>>>(Vw, 4, DD4);

    dim3 grid(D / CTA_N, M / CTA_M);   // (8, 128)
    gemm_mma<0><<<grid, 256, SMEM_BYTES>>>(b1, b2, nullptr, nullptr, 2 * D / KC);
    gemm_mma<1><<<grid, 256, SMEM_BYTES>>>(bV, nullptr, pe, out, D / KC);
}

// round 16
// speedup vs baseline: 4.6210x; 1.0178x over previous
#include <cuda_runtime.h>
#include <cstdint>
#include <cstddef>
#include <math.h>

// ---------------------------------------------------------------------------
// out[m,e], m<16384, e<2048
//   G1: pp = tanh( [LI|X](m,4096) . [W1;W2](e,4096)^T + b1 + b2 )
//   G2: out = sigmoid( pp . V^T + bV ) * pe
// tf32 mma.sync.m16n8k8.
// R15: activations feed G1 RAW (tf32 MMA HW truncates operand mantissas, so
// the explicit cvt.rna prepass only changed rounding mode; dropping it removes
// ~150us of prepass + a 256MB scratch round-trip at ~2e-4 rel_err cost).
// Weights stay RN-prerounded (cheap); g_pp RN-rounded in G1 epilogue.
// CTA 128x256, 8 warps of 64x64, K-chunk 32, 4-stage cp.async pipeline,
// single barrier per chunk, cp.async interleaved into MMA stream.
// ---------------------------------------------------------------------------
constexpr int D     = 2048;
constexpr int M     = 16384;
constexpr int CTA_M = 128;
constexpr int CTA_N = 256;
constexpr int KC    = 32;
constexpr int NSTG  = 4;
constexpr int A_WORDS = CTA_M * KC;               // 4096 (16 KB)
constexpr int B_WORDS = CTA_N * KC;               // 8192 (32 KB)
constexpr int STG_WORDS = A_WORDS + B_WORDS;      // 12288 (48 KB)
constexpr int SMEM_BYTES = NSTG * STG_WORDS * 4;  // 192 KB

__device__ float g_pp[(size_t)M * D];             // tf32-rounded pp
__device__ float g_w[3 * (size_t)D * D];          // tf32-rounded [W1 | W2 | V]

// ---------------------------------------------------------------------------
__device__ __forceinline__ uint32_t smem_u32(const void* p) {
    uint32_t a;
    asm("{ .reg .u64 t; cvta.to.shared.u64 t, %1; cvt.u32.u64 %0, t; }"
        : "=r"(a) : "l"(p));
    return a;
}

__device__ __forceinline__ void cp_async16(uint32_t s, const void* g) {
    asm volatile("cp.async.cg.shared.global [%0], [%1], 16;" :: "r"(s), "l"(g));
}

__device__ __forceinline__ void ldsm4(uint32_t* r, uint32_t addr) {
    asm volatile("ldmatrix.sync.aligned.m8n8.x4.shared.b16 {%0,%1,%2,%3}, [%4];"
                 : "=r"(r[0]), "=r"(r[1]), "=r"(r[2]), "=r"(r[3]) : "r"(addr));
}

__device__ __forceinline__ float to_tf32_f(float x) {
    uint32_t d;
    asm("cvt.rna.tf32.f32 %0, %1;" : "=r"(d) : "f"(x));
    return __uint_as_float(d);
}

__device__ __forceinline__ void mma_tf32(float* c, const uint32_t* a,
                                         uint32_t b0, uint32_t b1) {
    asm volatile(
        "mma.sync.aligned.m16n8k8.row.col.f32.tf32.tf32.f32 "
        "{%0,%1,%2,%3}, {%4,%5,%6,%7}, {%8,%9}, {%0,%1,%2,%3};"
        : "+f"(c[0]), "+f"(c[1]), "+f"(c[2]), "+f"(c[3])
        : "r"(a[0]), "r"(a[1]), "r"(a[2]), "r"(a[3]), "r"(b0), "r"(b1));
}

// swizzled word offset within a tile: row*32 + (kword ^ ((row&7)<<2))
__device__ __forceinline__ uint32_t swz(int row, int kw) {
    return (uint32_t)(row * 32 + (kw ^ ((row & 7) << 2)));
}

// ---------------------------------------------------------------------------
// Prepass (weights only): round src into g_w slot.
//   0: g_w[0]  1: g_w[D*D]  2: g_w[2*D*D]
// ---------------------------------------------------------------------------
__global__ void __launch_bounds__(256)
preround(const float* __restrict__ src, int dst_sel, size_t n4) {
    float* dst = g_w + (size_t)dst_sel * D * D;
    size_t i = (size_t)blockIdx.x * blockDim.x + threadIdx.x;
    size_t stride = (size_t)gridDim.x * blockDim.x;
    for (; i < n4; i += stride) {
        float4 v = ((const float4*)src)[i];
        v.x = to_tf32_f(v.x); v.y = to_tf32_f(v.y);
        v.z = to_tf32_f(v.z); v.w = to_tf32_f(v.w);
        ((float4*)dst)[i] = v;
    }
}

// ---------------------------------------------------------------------------
// Stage-load halves (A tile 128x32: 4 cp.async/thr; B tile 256x32: 8/thr)
// ---------------------------------------------------------------------------
__device__ __forceinline__ void load_A(uint32_t sbase, const float* __restrict__ Ap,
                                       int mBase, int koff, int tid) {
    #pragma unroll
    for (int i = 0; i < 4; i++) {
        int slot = tid + i * 256;
        int row = slot >> 3, c4 = slot & 7;
        cp_async16(sbase + swz(row, c4 * 4) * 4,
                   Ap + (size_t)(mBase + row) * D + koff + c4 * 4);
    }
}
__device__ __forceinline__ void load_B(uint32_t sbase, const float* __restrict__ Bp,
                                       int eBase, int koff, int tid) {
    #pragma unroll
    for (int i = 0; i < 8; i++) {
        int slot = tid + i * 256;
        int row = slot >> 3, c4 = slot & 7;
        cp_async16(sbase + (A_WORDS + swz(row, c4 * 4)) * 4,
                   Bp + (size_t)(eBase + row) * D + koff + c4 * 4);
    }
}

// ---------------------------------------------------------------------------
// MODE 0: G1 (A = li then x raw fp32; B = g_w[0],g_w[1]; epi tanh+round->g_pp)
// MODE 1: G2 (A = g_pp; B = g_w[2]; epi sigmoid * pe -> outp)
// ---------------------------------------------------------------------------
template <int MODE>
__global__ void __launch_bounds__(256, 1)
gemm_mma(const float* __restrict__ A0in, const float* __restrict__ A1in,
         const float* __restrict__ bias0, const float* __restrict__ bias1,
         const float* __restrict__ pe, float* __restrict__ outp, int NK)
{
    extern __shared__ float smem[];
    const uint32_t sb0 = smem_u32(smem);
    const int tid  = threadIdx.x;
    const int lane = tid & 31, wid = tid >> 5;
    const int wm = (wid & 1) * 64;
    const int wn = (wid >> 1) * 64;
    const int mBase = blockIdx.y * CTA_M;
    const int eBase = blockIdx.x * CTA_N;

    const float* Asrc0 = (MODE == 1) ? g_pp : A0in;
    const float* Asrc1 = (MODE == 1) ? g_pp : A1in;
    const float* Bsrc0 = (MODE == 1) ? g_w + 2 * (size_t)D * D : g_w;
    const float* Bsrc1 = (MODE == 1) ? g_w + 2 * (size_t)D * D : g_w + (size_t)D * D;

    float acc[4][8][4];
    #pragma unroll
    for (int i = 0; i < 4; i++)
        #pragma unroll
        for (int j = 0; j < 8; j++)
            #pragma unroll
            for (int k = 0; k < 4; k++) acc[i][j][k] = 0.f;

    auto pick = [&](int kc, const float*& Ap, const float*& Bp, int& koff) {
        if (kc < 64) { Ap = Asrc0; Bp = Bsrc0; koff = kc * KC; }
        else         { Ap = Asrc1; Bp = Bsrc1; koff = kc * KC - D; }
    };

    #pragma unroll
    for (int s = 0; s < NSTG - 1; ++s) {
        const float *Ap, *Bp; int koff;
        pick(s, Ap, Bp, koff);
        load_A(sb0 + s * STG_WORDS * 4, Ap, mBase, koff, tid);
        load_B(sb0 + s * STG_WORDS * 4, Bp, eBase, koff, tid);
        asm volatile("cp.async.commit_group;");
    }

    const int q = lane >> 3, r = lane & 7;

    #pragma unroll 1
    for (int kt = 0; kt < NK; ++kt) {
        asm volatile("cp.async.wait_group %0;" :: "n"(NSTG - 2));
        __syncthreads();

        const uint32_t stg = sb0 + (kt & 3) * STG_WORDS * 4;
        const int pf = kt + NSTG - 1;
        const bool do_pf = pf < NK;
        const float *Ap = nullptr, *Bp = nullptr; int koff = 0;
        if (do_pf) pick(pf, Ap, Bp, koff);
        const uint32_t pstg = sb0 + (pf & 3) * STG_WORDS * 4;

        uint32_t bf[8][4], af0[4][4], af1[4][4];

        // ---- B half 0 (ks 0..1) + A ks=0,1 ----
        #pragma unroll
        for (int nt = 0; nt < 8; ++nt)
            ldsm4(bf[nt], stg + (A_WORDS + swz(wn + nt * 8 + r, q * 4)) * 4);
        #pragma unroll
        for (int mt = 0; mt < 4; ++mt)
            ldsm4(af0[mt], stg + swz(wm + mt * 16 + (q & 1) * 8 + r, (q >> 1) * 4) * 4);
        if (do_pf) load_A(pstg, Ap, mBase, koff, tid);      // overlap LSU w/ MMA
        #pragma unroll
        for (int mt = 0; mt < 4; ++mt)
            ldsm4(af1[mt], stg + swz(wm + mt * 16 + (q & 1) * 8 + r, 8 + (q >> 1) * 4) * 4);

        #pragma unroll
        for (int mt = 0; mt < 4; ++mt)
            #pragma unroll
            for (int nt = 0; nt < 8; ++nt)
                mma_tf32(acc[mt][nt], af0[mt], bf[nt][0], bf[nt][1]);
        if (do_pf) load_B(pstg, Bp, eBase, koff, tid);
        #pragma unroll
        for (int mt = 0; mt < 4; ++mt)
            #pragma unroll
            for (int nt = 0; nt < 8; ++nt)
                mma_tf32(acc[mt][nt], af1[mt], bf[nt][2], bf[nt][3]);
        asm volatile("cp.async.commit_group;");

        // ---- B half 1 (ks 2..3) ----
        #pragma unroll
        for (int nt = 0; nt < 8; ++nt)
            ldsm4(bf[nt], stg + (A_WORDS + swz(wn + nt * 8 + r, 16 + q * 4)) * 4);
        #pragma unroll
        for (int mt = 0; mt < 4; ++mt)
            ldsm4(af0[mt], stg + swz(wm + mt * 16 + (q & 1) * 8 + r, 16 + (q >> 1) * 4) * 4);
        #pragma unroll
        for (int mt = 0; mt < 4; ++mt)
            ldsm4(af1[mt], stg + swz(wm + mt * 16 + (q & 1) * 8 + r, 24 + (q >> 1) * 4) * 4);

        #pragma unroll
        for (int mt = 0; mt < 4; ++mt)
            #pragma unroll
            for (int nt = 0; nt < 8; ++nt)
                mma_tf32(acc[mt][nt], af0[mt], bf[nt][0], bf[nt][1]);
        #pragma unroll
        for (int mt = 0; mt < 4; ++mt)
            #pragma unroll
            for (int nt = 0; nt < 8; ++nt)
                mma_tf32(acc[mt][nt], af1[mt], bf[nt][2], bf[nt][3]);
    }

    // ---------------- epilogue ----------------
    const int rq = lane >> 2, cq = lane & 3;
    #pragma unroll
    for (int mt = 0; mt < 4; ++mt) {
        const int row = mBase + wm + mt * 16 + rq;
        #pragma unroll
        for (int nt = 0; nt < 8; ++nt) {
            const int col = eBase + wn + nt * 8 + 2 * cq;
            const size_t o0 = (size_t)row * D + col;
            const size_t o1 = (size_t)(row + 8) * D + col;
            if (MODE == 0) {
                const float bs0 = bias0[col]     + bias1[col];
                const float bs1 = bias0[col + 1] + bias1[col + 1];
                float2 v0, v1;
                // RN-round pp here so G2's A operand is properly rounded
                v0.x = to_tf32_f(tanhf(acc[mt][nt][0] + bs0));
                v0.y = to_tf32_f(tanhf(acc[mt][nt][1] + bs1));
                v1.x = to_tf32_f(tanhf(acc[mt][nt][2] + bs0));
                v1.y = to_tf32_f(tanhf(acc[mt][nt][3] + bs1));
                *(float2*)&g_pp[o0] = v0;
                *(float2*)&g_pp[o1] = v1;
            } else {
                const float bs0 = bias0[col];
                const float bs1 = bias0[col + 1];
                const float2 p0 = *(const float2*)&pe[o0];
                const float2 p1 = *(const float2*)&pe[o1];
                float2 v0, v1;
                v0.x = p0.x / (1.f + __expf(-(acc[mt][nt][0] + bs0)));
                v0.y = p0.y / (1.f + __expf(-(acc[mt][nt][1] + bs1)));
                v1.x = p1.x / (1.f + __expf(-(acc[mt][nt][2] + bs0)));
                v1.y = p1.y / (1.f + __expf(-(acc[mt][nt][3] + bs1)));
                *(float2*)&outp[o0] = v0;
                *(float2*)&outp[o1] = v1;
            }
        }
    }
}

// ---------------------------------------------------------------------------
// Inputs (metadata order): 0:x 1:layer_input 2:position_embedding
// 3:encoder_padding_mask 4:langs 5:W1 6:b1 7:W2 8:b2 9:V 10:bV
// ---------------------------------------------------------------------------
extern "C" void kernel_launch(void* const* d_in, const int* in_sizes, int n_in,
                              void* d_out, int out_size)
{
    const float* x  = (const float*)d_in[0];
    const float* li = (const float*)d_in[1];
    const float* pe = (const float*)d_in[2];
    const float* W1 = (const float*)d_in[5];
    const float* b1 = (const float*)d_in[6];
    const float* W2 = (const float*)d_in[7];
    const float* b2 = (const float*)d_in[8];
    const float* Vw = (const float*)d_in[9];
    const float* bV = (const float*)d_in[10];
    float* out = (float*)d_out;

    static bool attr_done = false;
    if (!attr_done) {
        cudaFuncSetAttribute(gemm_mma<0>, cudaFuncAttributeMaxDynamicSharedMemorySize, SMEM_BYTES);
        cudaFuncSetAttribute(gemm_mma<1>, cudaFuncAttributeMaxDynamicSharedMemorySize, SMEM_BYTES);
        attr_done = true;
    }

    const size_t DD4 = (size_t)D * D / 4;
    preround<<<512, 256>>>(W1, 0, DD4);
    preround<<<512, 256>>>(W2, 1, DD4);
    preround<<<512, 256>>>(Vw, 2, DD4);

    dim3 grid(D / CTA_N, M / CTA_M);   // (8, 128)
    gemm_mma<0><<<grid, 256, SMEM_BYTES>>>(li, x, b1, b2, nullptr, nullptr, 2 * D / KC);
    gemm_mma<1><<<grid, 256, SMEM_BYTES>>>(nullptr, nullptr, bV, nullptr, pe, out, D / KC);
}